// round 10
// baseline (speedup 1.0000x reference)
#include <cuda_runtime.h>
#include <cstdint>

// Problem constants
#define BATCH 32
#define NPTS  65536          // N
#define GRIDW 128            // S / D1 = 384 / 3
#define CELLS (GRIDW * GRIDW)                    // 16384 per batch

#define NBLK  148            // persistent grid: <= SM count, all co-resident
#define NTHR  256
#define TILE_PTS 1024        // points per tile (256 thr x 4 pts)
#define TILES_TOTAL (BATCH * NPTS / TILE_PTS)    // 2048
#define MAX_TILES 14         // ceil(2048/148)
#define SMEM_BYTES (MAX_TILES * TILE_PTS * 4)    // 57344 B

// Compact accumulator [b][a0<<7|a1] float4 (8.4 MB). Zero at load (BSS);
// finalize self-cleans every window cell each call, and ALL splats are
// in-window, so it is always pristine at kernel start.
__device__ __align__(16) float4 g_accum[BATCH * CELLS];
// Per-batch exact key minima (memset to 0x7F7F7F7F each call)
__device__ int g_mins[BATCH * 2];
// Monotone barrier counter (never reset; epoch arithmetic handles replays)
__device__ unsigned g_bar;

// Separately-rounded dot3, left-associated ascending k (XLA loop-emitter order,
// NO fma contraction): fl(fl(fl(a0*b0) + fl(a1*b1)) + fl(a2*b2))
__device__ __forceinline__ float dot3_rn(float a0, float a1, float a2,
                                         float b0, float b1, float b2) {
    float s = __fmul_rn(a0, b0);
    s = __fadd_rn(s, __fmul_rn(a1, b1));
    s = __fadd_rn(s, __fmul_rn(a2, b2));
    return s;
}

// XLA:GPU-style f32 division: div.full.f32 (fast, <=2ulp, not IEEE-rounded)
__device__ __forceinline__ float fdiv_full(float a, float b) {
    float r;
    asm("div.full.f32 %0, %1, %2;" : "=f"(r) : "f"(a), "f"(b));
    return r;
}

// ceil-div by 3 for any sign
__device__ __forceinline__ int cdiv3(int a) {
    int q = a / 3;
    return q + ((a - q * 3) > 0);
}

// Exact per-point lattice computation (bit-identical to passing R5-R9).
__device__ __forceinline__ int point_coords(float p0, float p1, float p2,
                                            const float* __restrict__ tm,
                                            int& k0, int& k1) {
    const float e0 = dot3_rn(tm[0], tm[1], tm[2], p0, p1, p2);
    const float e1 = dot3_rn(tm[3], tm[4], tm[5], p0, p1, p2);
    const float e2 = dot3_rn(tm[6], tm[7], tm[8], p0, p1, p2);

    const float q0 = rintf(fdiv_full(e0, 3.0f));
    const float q1 = rintf(fdiv_full(e1, 3.0f));
    const float q2 = rintf(fdiv_full(e2, 3.0f));
    const float m0 = __fadd_rn(e0, -__fmul_rn(3.0f, q0));
    const float m1 = __fadd_rn(e1, -__fmul_rn(3.0f, q1));
    const float m2 = __fadd_rn(e2, -__fmul_rn(3.0f, q2));

    int r0 = (int)(m1 > m0) + (int)(m2 > m0);
    int r1 = (int)(m0 >= m1) + (int)(m2 > m1);

    int gq0 = (int)q0, gq1 = (int)q1, gq2 = (int)q2;
    const int rs = gq0 + gq1 + gq2;
    const int s  = (rs > 0) ? -1 : ((rs < 0) ? 1 : 0);

    const bool c0 = (rs > 0 && r0 >= 3 - rs) || (rs < 0 && r0 < -rs);
    const bool c1 = (rs > 0 && r1 >= 3 - rs) || (rs < 0 && r1 < -rs);
    gq0 += c0 ? s : 0;  r0 += (c0 ? 3 * s : 0) + rs;
    gq1 += c1 ? s : 0;  r1 += (c1 ? 3 * s : 0) + rs;

    const int rc0 = min(max(r0, 0), 2);
    const int rc1 = min(max(r1, 0), 2);

    k0 = 3 * gq0 - rc0;
    k1 = 3 * gq1 - rc1;
    return (gq0 & 0xFFFF) | (gq1 << 16);
}

// ---------------------------------------------------------------------------
// Fused persistent kernel: phase1 coords+k-min (pc1 read once, coords cached
// in smem) -> grid barrier -> phase2 splat with exact window offsets.
// ---------------------------------------------------------------------------
__global__ void __launch_bounds__(NTHR) fused_kernel(const float* __restrict__ pc1,
                                                     const float* __restrict__ feat,
                                                     const float* __restrict__ tmat) {
    extern __shared__ int4 s_coords[];   // [tile][256] packed coord quads
    const int tid  = threadIdx.x;
    const int warp = tid >> 5;
    const int lane = tid & 31;
    __shared__ int sm0[8], sm1[8];

    // ---------------- PHASE 1: coords + exact per-batch k-min ----------------
    int t = 0;
    for (int tile = blockIdx.x; tile < TILES_TOTAL; tile += NBLK, t++) {
        const int b  = tile >> 6;                       // 64 tiles per batch
        const int n0 = ((tile & 63) << 10) | (tid << 2);

        const float* pc = pc1 + ((size_t)b * 3) * NPTS;
        const float4 v0 = __ldcs(reinterpret_cast<const float4*>(pc + n0));
        const float4 v1 = __ldcs(reinterpret_cast<const float4*>(pc + NPTS + n0));
        const float4 v2 = __ldcs(reinterpret_cast<const float4*>(pc + 2 * NPTS + n0));

        float tm[9];
        const float* tmg = tmat + b * 9;
        #pragma unroll
        for (int i = 0; i < 9; i++) tm[i] = __ldg(tmg + i);

        int4 packed;
        int k0a, k1a, k0b, k1b, k0c, k1c, k0d, k1d;
        packed.x = point_coords(v0.x, v1.x, v2.x, tm, k0a, k1a);
        packed.y = point_coords(v0.y, v1.y, v2.y, tm, k0b, k1b);
        packed.z = point_coords(v0.z, v1.z, v2.z, tm, k0c, k1c);
        packed.w = point_coords(v0.w, v1.w, v2.w, tm, k0d, k1d);

        s_coords[t * NTHR + tid] = packed;

        const int k0 = min(min(k0a, k0b), min(k0c, k0d));
        const int k1 = min(min(k1a, k1b), min(k1c, k1d));

        // block-level min for this tile, then 2 atomicMin
        int w0 = __reduce_min_sync(0xFFFFFFFFu, k0);
        int w1 = __reduce_min_sync(0xFFFFFFFFu, k1);
        if (lane == 0) { sm0[warp] = w0; sm1[warp] = w1; }
        __syncthreads();
        if (tid == 0) {
            int b0 = sm0[0], b1 = sm1[0];
            #pragma unroll
            for (int w = 1; w < 8; w++) { b0 = min(b0, sm0[w]); b1 = min(b1, sm1[w]); }
            atomicMin(&g_mins[b * 2 + 0], b0);
            atomicMin(&g_mins[b * 2 + 1], b1);
        }
        __syncthreads();   // protect sm0/sm1 reuse next tile
    }
    const int my_tiles = t;

    // ---------------- grid barrier (monotone epoch counter) ----------------
    __threadfence();
    __syncthreads();
    if (tid == 0) {
        const unsigned arrival = atomicAdd(&g_bar, 1u);
        const unsigned target  = arrival - (arrival % NBLK) + NBLK;
        while ((int)(atomicAdd(&g_bar, 0u) - target) < 0) { __nanosleep(64); }
        __threadfence();
    }
    __syncthreads();

    // ---------------- PHASE 2: splat with exact window offsets ----------------
    t = 0;
    for (int tile = blockIdx.x; tile < TILES_TOTAL; tile += NBLK, t++) {
        const int b  = tile >> 6;
        const int n0 = ((tile & 63) << 10) | (tid << 2);

        const int off0 = cdiv3(__ldcg(&g_mins[b * 2 + 0]));
        const int off1 = cdiv3(__ldcg(&g_mins[b * 2 + 1]));

        const float* f = feat + ((size_t)b * 3) * NPTS;
        const float4 f0 = __ldcs(reinterpret_cast<const float4*>(f + n0));
        const float4 f1 = __ldcs(reinterpret_cast<const float4*>(f + NPTS + n0));
        const float4 f2 = __ldcs(reinterpret_cast<const float4*>(f + 2 * NPTS + n0));

        const int4 packed = s_coords[t * NTHR + tid];

        float4* acc = g_accum + ((size_t)b << 14);

        const int pk[4] = {packed.x, packed.y, packed.z, packed.w};
        const float x0[4] = {f0.x, f0.y, f0.z, f0.w};
        const float x1[4] = {f1.x, f1.y, f1.z, f1.w};
        const float x2[4] = {f2.x, f2.y, f2.z, f2.w};

        #pragma unroll
        for (int i = 0; i < 4; i++) {
            const int a0 = ((int)(short)(pk[i] & 0xFFFF)) - off0;
            const int a1 = (pk[i] >> 16) - off1;
            if ((unsigned)a0 < (unsigned)GRIDW && (unsigned)a1 < (unsigned)GRIDW) {
                atomicAdd(acc + ((a0 << 7) | a1), make_float4(x0[i], x1[i], x2[i], 0.f));
            }
        }
    }
    (void)my_tiles;
}

// ---------------------------------------------------------------------------
// Finalize: read the compact window, self-clean to zero, write output.
// grid = 512 x 256; 4 cells (one row-quad) per thread
// ---------------------------------------------------------------------------
__global__ void __launch_bounds__(256) finalize_kernel(float* __restrict__ out) {
    const int t = blockIdx.x * 256 + threadIdx.x;   // 0 .. 131071
    float4* acc = g_accum + ((size_t)t << 2);
    const float4 c0 = acc[0];
    const float4 c1 = acc[1];
    const float4 c2 = acc[2];
    const float4 c3 = acc[3];

    const float4 z = make_float4(0.f, 0.f, 0.f, 0.f);
    acc[0] = z; acc[1] = z; acc[2] = z; acc[3] = z;

    float4* o = reinterpret_cast<float4*>(out + (size_t)t * 12);
    o[0] = make_float4(c0.x, c0.y, c0.z, c1.x);
    o[1] = make_float4(c1.y, c1.z, c2.x, c2.y);
    o[2] = make_float4(c2.z, c3.x, c3.y, c3.z);
}

// ---------------------------------------------------------------------------
extern "C" void kernel_launch(void* const* d_in, const int* in_sizes, int n_in,
                              void* d_out, int out_size) {
    const float* pc1   = (const float*)d_in[0];
    const float* feat  = (const float*)d_in[1];
    const float* tmat  = (const float*)d_in[2];
    float* out = (float*)d_out;

    (void)in_sizes; (void)n_in; (void)out_size;

    static bool attr_set = false;
    if (!attr_set) {
        cudaFuncSetAttribute(fused_kernel,
                             cudaFuncAttributeMaxDynamicSharedMemorySize, SMEM_BYTES);
        attr_set = true;
    }

    void* mins_ptr = nullptr;
    cudaGetSymbolAddress(&mins_ptr, g_mins);
    cudaMemsetAsync(mins_ptr, 0x7F, sizeof(int) * BATCH * 2);   // large positive ints

    fused_kernel<<<NBLK, NTHR, SMEM_BYTES>>>(pc1, feat, tmat);
    finalize_kernel<<<512, 256>>>(out);
}

// round 11
// speedup vs baseline: 2.1050x; 2.1050x over previous
#include <cuda_runtime.h>
#include <cstdint>

// Problem constants
#define BATCH 32
#define NPTS  65536          // N
#define GRIDW 128            // S / D1 = 384 / 3
#define PADW  140            // padded accumulator width (>= 134 needed, margin)
#define PCELLS (PADW * PADW)                   // 19600
#define ACC_F4 (BATCH * PCELLS)                // 627,200 float4 cells (10.0 MB)

// Padded accumulator: [b][a0*140+a1] as float4 (16B); zeroed in anchor pass.
__device__ __align__(16) float4 g_accum[ACC_F4];
// Per-batch mins: [b][0]=k0min [b][1]=k1min [b][2]=floor(e0)min [b][3]=floor(e1)min
__device__ int g_mins[BATCH * 4];

// Separately-rounded dot3, left-associated ascending k (XLA loop-emitter order,
// NO fma contraction): fl(fl(fl(a0*b0) + fl(a1*b1)) + fl(a2*b2))
__device__ __forceinline__ float dot3_rn(float a0, float a1, float a2,
                                         float b0, float b1, float b2) {
    float s = __fmul_rn(a0, b0);
    s = __fadd_rn(s, __fmul_rn(a1, b1));
    s = __fadd_rn(s, __fmul_rn(a2, b2));
    return s;
}

// XLA:GPU-style f32 division: div.full.f32 (fast, <=2ulp, not IEEE-rounded)
__device__ __forceinline__ float fdiv_full(float a, float b) {
    float r;
    asm("div.full.f32 %0, %1, %2;" : "=f"(r) : "f"(a), "f"(b));
    return r;
}

__device__ __forceinline__ void block_min2_atomic(int v0, int v1, int* dst0, int* dst1) {
    int w0 = __reduce_min_sync(0xFFFFFFFFu, v0);
    int w1 = __reduce_min_sync(0xFFFFFFFFu, v1);
    __shared__ int sm0[8], sm1[8];
    const int warp = threadIdx.x >> 5;
    const int lane = threadIdx.x & 31;
    if (lane == 0) { sm0[warp] = w0; sm1[warp] = w1; }
    __syncthreads();
    if (threadIdx.x == 0) {
        int b0 = sm0[0], b1 = sm1[0];
        #pragma unroll
        for (int w = 1; w < 8; w++) { b0 = min(b0, sm0[w]); b1 = min(b1, sm1[w]); }
        atomicMin(dst0, b0);
        atomicMin(dst1, b1);
    }
}

// floor-div by 3 for any sign
__device__ __forceinline__ int fdiv3(int a) {
    int q = a / 3;
    return q - ((a - q * 3) < 0);
}
// ceil-div by 3 for any sign
__device__ __forceinline__ int cdiv3(int a) {
    int q = a / 3;
    return q + ((a - q * 3) > 0);
}
// anchor from floor(e)-min:  floor((min_floor_e - 8) / 3)
__device__ __forceinline__ int anchor_of(int efloor_min) {
    return fdiv3(efloor_min - 8);
}

// ---------------------------------------------------------------------------
// Kernel 1: anchor pass — min of floor(e0), floor(e1); zero the accumulator.
// grid = BATCH*32 x 256, 8 points/thread (6 independent LDG.128 in flight)
// ---------------------------------------------------------------------------
__global__ void __launch_bounds__(256) anchor_kernel(const float* __restrict__ pc1,
                                                     const float* __restrict__ tmat) {
    const int b  = blockIdx.x >> 5;
    const int n0 = ((blockIdx.x & 31) << 11) | (threadIdx.x << 3);   // 8 pts
    const int gidx = blockIdx.x * 256 + threadIdx.x;                  // 0..262143

    const float* pc = pc1 + ((size_t)b * 3) * NPTS;
    const float4 v0a = __ldcs(reinterpret_cast<const float4*>(pc + n0));
    const float4 v0b = __ldcs(reinterpret_cast<const float4*>(pc + n0 + 4));
    const float4 v1a = __ldcs(reinterpret_cast<const float4*>(pc + NPTS + n0));
    const float4 v1b = __ldcs(reinterpret_cast<const float4*>(pc + NPTS + n0 + 4));
    const float4 v2a = __ldcs(reinterpret_cast<const float4*>(pc + 2 * NPTS + n0));
    const float4 v2b = __ldcs(reinterpret_cast<const float4*>(pc + 2 * NPTS + n0 + 4));

    // zero the accumulator while loads are in flight (627,200 / 262,144 -> 3 iters)
    const float4 z = make_float4(0.f, 0.f, 0.f, 0.f);
    #pragma unroll
    for (int i = gidx; i < ACC_F4; i += BATCH * 32 * 256) g_accum[i] = z;

    const float* tm = tmat + b * 9;
    const float t00 = __ldg(tm + 0), t01 = __ldg(tm + 1), t02 = __ldg(tm + 2);
    const float t10 = __ldg(tm + 3), t11 = __ldg(tm + 4), t12 = __ldg(tm + 5);

    const float p0[8] = {v0a.x, v0a.y, v0a.z, v0a.w, v0b.x, v0b.y, v0b.z, v0b.w};
    const float p1[8] = {v1a.x, v1a.y, v1a.z, v1a.w, v1b.x, v1b.y, v1b.z, v1b.w};
    const float p2[8] = {v2a.x, v2a.y, v2a.z, v2a.w, v2b.x, v2b.y, v2b.z, v2b.w};

    int e0m = 0x7FFFFFFF, e1m = 0x7FFFFFFF;
    #pragma unroll
    for (int i = 0; i < 8; i++) {
        const float e0 = dot3_rn(t00, t01, t02, p0[i], p1[i], p2[i]);
        const float e1 = dot3_rn(t10, t11, t12, p0[i], p1[i], p2[i]);
        e0m = min(e0m, (int)floorf(e0));
        e1m = min(e1m, (int)floorf(e1));
    }
    block_min2_atomic(e0m, e1m, &g_mins[b * 4 + 2], &g_mins[b * 4 + 3]);
}

// ---------------------------------------------------------------------------
// Kernel 2: fused coords + exact k-min + splat into padded accumulator.
// grid = BATCH*32 x 256, 8 points/thread (12 independent LDG.128 in flight)
// ---------------------------------------------------------------------------
__global__ void __launch_bounds__(256) splat_kernel(const float* __restrict__ pc1,
                                                    const float* __restrict__ feat,
                                                    const float* __restrict__ tmat) {
    const int b  = blockIdx.x >> 5;
    const int n0 = ((blockIdx.x & 31) << 11) | (threadIdx.x << 3);   // 8 pts

    const int anch0 = anchor_of(g_mins[b * 4 + 2]);
    const int anch1 = anchor_of(g_mins[b * 4 + 3]);

    const float* pc = pc1 + ((size_t)b * 3) * NPTS;
    const float4 v0a = __ldcs(reinterpret_cast<const float4*>(pc + n0));
    const float4 v0b = __ldcs(reinterpret_cast<const float4*>(pc + n0 + 4));
    const float4 v1a = __ldcs(reinterpret_cast<const float4*>(pc + NPTS + n0));
    const float4 v1b = __ldcs(reinterpret_cast<const float4*>(pc + NPTS + n0 + 4));
    const float4 v2a = __ldcs(reinterpret_cast<const float4*>(pc + 2 * NPTS + n0));
    const float4 v2b = __ldcs(reinterpret_cast<const float4*>(pc + 2 * NPTS + n0 + 4));

    const float* f = feat + ((size_t)b * 3) * NPTS;
    const float4 f0a = __ldcs(reinterpret_cast<const float4*>(f + n0));
    const float4 f0b = __ldcs(reinterpret_cast<const float4*>(f + n0 + 4));
    const float4 f1a = __ldcs(reinterpret_cast<const float4*>(f + NPTS + n0));
    const float4 f1b = __ldcs(reinterpret_cast<const float4*>(f + NPTS + n0 + 4));
    const float4 f2a = __ldcs(reinterpret_cast<const float4*>(f + 2 * NPTS + n0));
    const float4 f2b = __ldcs(reinterpret_cast<const float4*>(f + 2 * NPTS + n0 + 4));

    float tm[9];
    const float* tmg = tmat + b * 9;
    #pragma unroll
    for (int i = 0; i < 9; i++) tm[i] = __ldg(tmg + i);

    float4* acc = g_accum + (size_t)b * PCELLS;

    const float p0[8] = {v0a.x, v0a.y, v0a.z, v0a.w, v0b.x, v0b.y, v0b.z, v0b.w};
    const float p1[8] = {v1a.x, v1a.y, v1a.z, v1a.w, v1b.x, v1b.y, v1b.z, v1b.w};
    const float p2[8] = {v2a.x, v2a.y, v2a.z, v2a.w, v2b.x, v2b.y, v2b.z, v2b.w};
    const float x0[8] = {f0a.x, f0a.y, f0a.z, f0a.w, f0b.x, f0b.y, f0b.z, f0b.w};
    const float x1[8] = {f1a.x, f1a.y, f1a.z, f1a.w, f1b.x, f1b.y, f1b.z, f1b.w};
    const float x2[8] = {f2a.x, f2a.y, f2a.z, f2a.w, f2b.x, f2b.y, f2b.z, f2b.w};

    int k0min = 0x7FFFFFFF, k1min = 0x7FFFFFFF;

    #pragma unroll
    for (int i = 0; i < 8; i++) {
        // ---- exact per-point lattice computation (bit-identical to R5-R10) ----
        const float e0 = dot3_rn(tm[0], tm[1], tm[2], p0[i], p1[i], p2[i]);
        const float e1 = dot3_rn(tm[3], tm[4], tm[5], p0[i], p1[i], p2[i]);
        const float e2 = dot3_rn(tm[6], tm[7], tm[8], p0[i], p1[i], p2[i]);

        const float q0 = rintf(fdiv_full(e0, 3.0f));
        const float q1 = rintf(fdiv_full(e1, 3.0f));
        const float q2 = rintf(fdiv_full(e2, 3.0f));
        const float m0 = __fadd_rn(e0, -__fmul_rn(3.0f, q0));
        const float m1 = __fadd_rn(e1, -__fmul_rn(3.0f, q1));
        const float m2 = __fadd_rn(e2, -__fmul_rn(3.0f, q2));

        int r0 = (int)(m1 > m0) + (int)(m2 > m0);
        int r1 = (int)(m0 >= m1) + (int)(m2 > m1);

        int gq0 = (int)q0, gq1 = (int)q1, gq2 = (int)q2;
        const int rs = gq0 + gq1 + gq2;
        const int s  = (rs > 0) ? -1 : ((rs < 0) ? 1 : 0);

        const bool c0 = (rs > 0 && r0 >= 3 - rs) || (rs < 0 && r0 < -rs);
        const bool c1 = (rs > 0 && r1 >= 3 - rs) || (rs < 0 && r1 < -rs);
        gq0 += c0 ? s : 0;  r0 += (c0 ? 3 * s : 0) + rs;
        gq1 += c1 ? s : 0;  r1 += (c1 ? 3 * s : 0) + rs;

        const int rc0 = min(max(r0, 0), 2);
        const int rc1 = min(max(r1, 0), 2);

        k0min = min(k0min, 3 * gq0 - rc0);
        k1min = min(k1min, 3 * gq1 - rc1);

        // ---- splat at anchored coords (pad cells never read back) ----
        const int a0 = gq0 - anch0;
        const int a1 = gq1 - anch1;
        if ((unsigned)a0 < (unsigned)PADW && (unsigned)a1 < (unsigned)PADW) {
            atomicAdd(acc + (a0 * PADW + a1), make_float4(x0[i], x1[i], x2[i], 0.f));
        }
    }

    block_min2_atomic(k0min, k1min, &g_mins[b * 4 + 0], &g_mins[b * 4 + 1]);
}

// ---------------------------------------------------------------------------
// Kernel 3: finalize — gather exact 128x128 window, write 3 floats/cell.
// grid = 512 x 256; 4 cells (one row-quad) per thread
// ---------------------------------------------------------------------------
__global__ void __launch_bounds__(256) finalize_kernel(float* __restrict__ out) {
    const int t = blockIdx.x * 256 + threadIdx.x;  // 0 .. 131071
    const int b = t >> 12;                         // 4096 threads per batch
    const int c = t & 4095;
    const int i = c >> 5;                          // row 0..127
    const int j = (c & 31) << 2;                   // col 0,4,..,124

    const int r0 = cdiv3(g_mins[b * 4 + 0]) - anchor_of(g_mins[b * 4 + 2]);
    const int r1 = cdiv3(g_mins[b * 4 + 1]) - anchor_of(g_mins[b * 4 + 3]);

    const float4* acc = g_accum + (size_t)b * PCELLS + (r0 + i) * PADW + (r1 + j);
    const float4 c0 = acc[0];
    const float4 c1 = acc[1];
    const float4 c2 = acc[2];
    const float4 c3 = acc[3];

    float4* o = reinterpret_cast<float4*>(out + (size_t)t * 12);
    o[0] = make_float4(c0.x, c0.y, c0.z, c1.x);
    o[1] = make_float4(c1.y, c1.z, c2.x, c2.y);
    o[2] = make_float4(c2.z, c3.x, c3.y, c3.z);
}

// ---------------------------------------------------------------------------
extern "C" void kernel_launch(void* const* d_in, const int* in_sizes, int n_in,
                              void* d_out, int out_size) {
    const float* pc1   = (const float*)d_in[0];
    const float* feat  = (const float*)d_in[1];
    const float* tmat  = (const float*)d_in[2];
    float* out = (float*)d_out;

    (void)in_sizes; (void)n_in; (void)out_size;

    void* mins_ptr = nullptr;
    cudaGetSymbolAddress(&mins_ptr, g_mins);
    cudaMemsetAsync(mins_ptr, 0x7F, sizeof(int) * BATCH * 4);   // large positive ints

    anchor_kernel<<<BATCH * 32, 256>>>(pc1, tmat);
    splat_kernel<<<BATCH * 32, 256>>>(pc1, feat, tmat);
    finalize_kernel<<<512, 256>>>(out);
}